// round 10
// baseline (speedup 1.0000x reference)
#include <cuda_runtime.h>
#include <math.h>

#define BB 64
#define GRID 128
#define TPB 256
#define NSLOT 128
#define NST (BB*NSLOT*512)

__device__ float g_H[NST];
__device__ float g_C[NST];
// vV cache: [b][slot][side][2560] ; side0 = W_l@h, side1 = W_r@h
__device__ float g_V[BB*NSLOT*2*2560];
__device__ float g_cwp[2][128*128];   // cw partials, parity double-buffered
__device__ float g_cw0[BB*63];
__device__ unsigned g_bar[4];

__device__ __forceinline__ float sigm(float x){ return 1.0f/(1.0f+expf(-x)); }

__device__ __forceinline__ void ffma2(float2 &acc, float2 a, float2 b){
    asm("fma.rn.f32x2 %0, %1, %2, %0;"
        : "+l"(reinterpret_cast<unsigned long long&>(acc))
        : "l"(reinterpret_cast<unsigned long long&>(a)),
          "l"(reinterpret_cast<unsigned long long&>(b)));
}

__device__ __forceinline__ void grid_barrier(unsigned target){
    __syncthreads();
    if (threadIdx.x == 0){
        asm volatile("red.release.gpu.global.add.u32 [%0], 1;"
                     :: "l"(&g_bar[blockIdx.x & 3]) : "memory");
        unsigned v0, v1, v2, v3;
        do {
            asm volatile("ld.acquire.gpu.global.u32 %0, [%1];" : "=r"(v0) : "l"(&g_bar[0]) : "memory");
            asm volatile("ld.acquire.gpu.global.u32 %0, [%1];" : "=r"(v1) : "l"(&g_bar[1]) : "memory");
            asm volatile("ld.acquire.gpu.global.u32 %0, [%1];" : "=r"(v2) : "l"(&g_bar[2]) : "memory");
            asm volatile("ld.acquire.gpu.global.u32 %0, [%1];" : "=r"(v3) : "l"(&g_bar[3]) : "memory");
        } while (v0 + v1 + v2 + v3 < target);
    }
    __syncthreads();
}

// ---------------------------------------------------------------------------
// Word GEMM (f32x2, transposed W tile); also zeroes the grid-barrier counters
// ---------------------------------------------------------------------------
__global__ __launch_bounds__(256) void word_gemm(
    const float* __restrict__ x, const float* __restrict__ w,
    const float* __restrict__ bias)
{
    if (blockIdx.x == 0 && blockIdx.y == 0 && threadIdx.x < 4)
        g_bar[threadIdx.x] = 0u;

    __shared__ float As[64][33];
    __shared__ float Wt[32][68];
    int tid = threadIdx.x;
    int tx = tid & 15, ty = tid >> 4;
    int m0 = blockIdx.y * 64;
    int c0 = blockIdx.x * 64;
    const int lr = tid >> 5, kkld = tid & 31;

    float2 acc[4][2];
    #pragma unroll
    for (int r = 0; r < 4; r++){ acc[r][0] = make_float2(0.f,0.f); acc[r][1] = make_float2(0.f,0.f); }

    for (int k0 = 0; k0 < 512; k0 += 32) {
        #pragma unroll
        for (int t = 0; t < 8; t++) {
            int r = lr + 8 * t;
            As[r][kkld] = x[(m0 + r) * 512 + k0 + kkld];
            Wt[kkld][r] = w[(c0 + r) * 512 + k0 + kkld];
        }
        __syncthreads();
        #pragma unroll
        for (int kk = 0; kk < 32; kk++) {
            float4 wv = *(const float4*)&Wt[kk][tx * 4];
            #pragma unroll
            for (int r = 0; r < 4; r++) {
                float a = As[ty * 4 + r][kk];
                ffma2(acc[r][0], make_float2(a, a), make_float2(wv.x, wv.y));
                ffma2(acc[r][1], make_float2(a, a), make_float2(wv.z, wv.w));
            }
        }
        __syncthreads();
    }
    #pragma unroll
    for (int r = 0; r < 4; r++) {
        int m = m0 + ty * 4 + r;
        int b = m >> 6, leaf = m & 63;
        int base = (b * NSLOT + leaf) * 512;
        #pragma unroll
        for (int c2 = 0; c2 < 2; c2++) {
            #pragma unroll
            for (int e = 0; e < 2; e++) {
                int col = c0 + tx * 4 + c2 * 2 + e;
                float v = (e ? acc[r][c2].y : acc[r][c2].x) + bias[col];
                if (col < 512) g_H[base + col] = v;
                else           g_C[base + col - 512] = v;
            }
        }
    }
}

// ---------------------------------------------------------------------------
// vV for all 4096 leaf nodes. 128 persistent blocks: W resident in smem
// (loaded once), 32 m-tiles each, double-buffered A, 1 sync per 64-k chunk.
// ---------------------------------------------------------------------------
#define VW_STRIDE 516
#define VA_STRIDE 68
#define VW_F  (40*VW_STRIDE)
#define VAB_F (128*VA_STRIDE)
#define VV_SMEM ((VW_F + 2*VAB_F)*4)

__global__ __launch_bounds__(256) void vv_full(const float* __restrict__ wcomp)
{
    extern __shared__ float vsm[];
    float* Wr  = vsm;                 // [g*8+hh][512+pad]
    float* Ab0 = vsm + VW_F;
    float* Ab1 = vsm + VW_F + VAB_F;

    const int tid = threadIdx.x;
    const int tx = tid & 7, ty = tid >> 3;
    const int side = blockIdx.x & 1;
    const int h0 = (blockIdx.x >> 1) * 8;
    const int lrow = tid >> 4, lq4 = tid & 15;

    // resident W: 40 rows x 512
    for (int idx = tid; idx < 40 * 512; idx += TPB) {
        int r2 = idx >> 9, k = idx & 511;
        int g = r2 >> 3, hh = r2 & 7;
        Wr[r2 * VW_STRIDE + k] = wcomp[(g * 512 + h0 + hh) * 1024 + side * 512 + k];
    }
    __syncthreads();

    for (int mt = 0; mt < 32; mt++) {
        const int m0 = mt * 128;
        int abase[8];
        #pragma unroll
        for (int ii = 0; ii < 8; ii++) {
            int row = m0 + lrow + 16 * ii;
            int b = row >> 6, leaf = row & 63;
            abase[ii] = (b * NSLOT + leaf) * 512;
        }

        float2 acc[4][5];
        #pragma unroll
        for (int r = 0; r < 4; r++)
            #pragma unroll
            for (int g = 0; g < 5; g++) acc[r][g] = make_float2(0.f, 0.f);

        float4 pf[8];
        #pragma unroll
        for (int ii = 0; ii < 8; ii++)
            pf[ii] = __ldcg((const float4*)&g_H[abase[ii] + lq4 * 4]);
        #pragma unroll
        for (int ii = 0; ii < 8; ii++)
            ((float4*)(Ab0 + (lrow + 16 * ii) * VA_STRIDE))[lq4] = pf[ii];
        __syncthreads();

        for (int c = 0; c < 8; c++) {
            if (c < 7) {
                #pragma unroll
                for (int ii = 0; ii < 8; ii++)
                    pf[ii] = __ldcg((const float4*)&g_H[abase[ii] + (c + 1) * 64 + lq4 * 4]);
            }
            const float* A = (c & 1) ? Ab1 : Ab0;
            #pragma unroll 4
            for (int k4 = 0; k4 < 16; k4++) {
                float4 wv[5];
                #pragma unroll
                for (int g = 0; g < 5; g++)
                    wv[g] = ((const float4*)(Wr + (g * 8 + tx) * VW_STRIDE))[c * 16 + k4];
                #pragma unroll
                for (int r = 0; r < 4; r++) {
                    float4 av = ((const float4*)(A + (ty * 4 + r) * VA_STRIDE))[k4];
                    #pragma unroll
                    for (int g = 0; g < 5; g++) {
                        ffma2(acc[r][g], make_float2(av.x, av.y), make_float2(wv[g].x, wv[g].y));
                        ffma2(acc[r][g], make_float2(av.z, av.w), make_float2(wv[g].z, wv[g].w));
                    }
                }
            }
            if (c < 7) {
                float* An = (c & 1) ? Ab0 : Ab1;
                #pragma unroll
                for (int ii = 0; ii < 8; ii++)
                    ((float4*)(An + (lrow + 16 * ii) * VA_STRIDE))[lq4] = pf[ii];
            }
            __syncthreads();
        }

        #pragma unroll
        for (int r = 0; r < 4; r++) {
            int row = m0 + ty * 4 + r;
            int b = row >> 6, leaf = row & 63;
            int vbase = ((b * NSLOT + leaf) * 2 + side) * 2560;
            #pragma unroll
            for (int g = 0; g < 5; g++)
                g_V[vbase + g * 512 + h0 + tx] = acc[r][g].x + acc[r][g].y;
        }
    }
}

// ---------------------------------------------------------------------------
// Iter-0 candidates from vV: h/c + cw0.  4032 blocks.
// ---------------------------------------------------------------------------
__global__ __launch_bounds__(256) void pair_epi(
    const float* __restrict__ bcomp, const float* __restrict__ q)
{
    __shared__ float red[8];
    int pb = blockIdx.x;
    int b = pb / 63, j = pb - b * 63;
    int nl = b * NSLOT + j, nr = nl + 1, ns = b * NSLOT + 64 + j;
    int tid = threadIdx.x, lane = tid & 31, warp = tid >> 5;
    float p = 0.f;
    #pragma unroll
    for (int half = 0; half < 2; half++) {
        int hd = tid + 256 * half;
        float vg[5];
        #pragma unroll
        for (int g = 0; g < 5; g++)
            vg[g] = __ldcg(&g_V[(nl * 2 + 0) * 2560 + g * 512 + hd])
                  + __ldcg(&g_V[(nr * 2 + 1) * 2560 + g * 512 + hd])
                  + bcomp[g * 512 + hd];
        float cl = __ldcg(&g_C[nl * 512 + hd]), cr = __ldcg(&g_C[nr * 512 + hd]);
        float cn = cl * sigm(vg[1] + 1.f) + cr * sigm(vg[2] + 1.f)
                 + tanhf(vg[3]) * sigm(vg[0]);
        float hn = sigm(vg[4]) * tanhf(cn);
        g_H[ns * 512 + hd] = hn;
        g_C[ns * 512 + hd] = cn;
        p += hn * q[hd];
    }
    #pragma unroll
    for (int o = 16; o > 0; o >>= 1) p += __shfl_xor_sync(0xffffffffu, p, o);
    if (lane == 0) red[warp] = p;
    __syncthreads();
    if (tid == 0) {
        float s = 0.f;
        #pragma unroll
        for (int w = 0; w < 8; w++) s += red[w];
        g_cw0[b * 63 + j] = s;
    }
}

// ---------------------------------------------------------------------------
// Persistent loop
// ---------------------------------------------------------------------------
#define W_STRIDE 516
#define A_STRIDE 68
#define WRES_F   (40*W_STRIDE)
#define ASB_F    (64*A_STRIDE)
#define SVN_F    (64*40)
#define SMEM_BYTES ((WRES_F + 2*ASB_F + SVN_F)*4)

__global__ __launch_bounds__(TPB, 1) void tree_loop(
    const int* __restrict__ length, const float* __restrict__ q,
    const float* __restrict__ wcomp, const float* __restrict__ bcomp,
    float* __restrict__ out)
{
    extern __shared__ float smem[];
    float* Wres  = smem;
    float* Asb0  = smem + WRES_F;
    float* Asb1  = smem + WRES_F + ASB_F;
    float* sVnew = smem + WRES_F + 2*ASB_F;

    __shared__ unsigned char s_vh[BB][64];
    __shared__ unsigned char s_pk[BB][64];
    __shared__ float s_cw[BB][64];
    __shared__ int2  s_fresh[BB];
    __shared__ int   s_sel[BB];
    __shared__ int   s_nodeidx[BB];
    __shared__ int4  s_rows[128];
    __shared__ unsigned char s_rb[128], s_rln[128], s_rrn[128];
    __shared__ int   s_rcnt[BB], s_roff[BB], s_len[BB];
    __shared__ int   s_nrows, s_maxlen;

    const int tid = threadIdx.x, blk = blockIdx.x;
    const int u = tid & 3, v = tid >> 2;
    const int lane = tid & 31, warp = tid >> 5;
    const int hg = blk * 4 + u;

    for (int idx = tid; idx < 40 * 512; idx += TPB) {
        int r2 = idx >> 9, k = idx & 511;
        int side = r2 / 20, rem = r2 % 20, g = rem >> 2, hgo = rem & 3;
        Wres[r2 * W_STRIDE + k] = wcomp[(g * 512 + blk * 4 + hgo) * 1024 + side * 512 + k];
    }
    const float qv  = q[hg];
    const float bi  = bcomp[hg],        bfl = bcomp[512 + hg], bfr = bcomp[1024 + hg];
    const float bu  = bcomp[1536 + hg], bo  = bcomp[2048 + hg];

    for (int t = tid; t < BB * 64; t += TPB) {
        int b = t >> 6, j = t & 63;
        s_vh[b][j] = (unsigned char)j;
        s_pk[b][j] = (unsigned char)(64 + j);
        s_cw[b][j] = (j < 63) ? __ldcg(&g_cw0[b * 63 + j]) : -1e9f;
    }
    if (tid < BB) { s_len[tid] = length[tid]; s_fresh[tid] = make_int2(-1, -1); }
    __syncthreads();
    if (tid == 0) {
        int m = 0;
        for (int b = 0; b < BB; b++) if (s_len[b] > m) m = s_len[b];
        s_maxlen = m;
    }
    __syncthreads();
    const int maxlen = s_maxlen;

    unsigned target = 0;

    for (int i = 0; i < 63; i++) {
        if (i + 1 >= maxlen) break;
        const int n = 63 - i;

        // ---- (a) fold cw partials ----
        if (i > 0) {
            const float* cwsrc = g_cwp[i & 1];
            float4 vbuf[16];
            int    pbuf[16];
            #pragma unroll
            for (int rr = 0; rr < 16; rr++) {
                int rid = warp + 8 * rr;
                int b = rid >> 1;
                int2 fr = s_fresh[b];
                int pidx = (rid & 1) ? fr.y : fr.x;
                pbuf[rr] = pidx;
                vbuf[rr] = (pidx >= 0)
                         ? __ldcg((const float4*)&cwsrc[rid * 128 + lane * 4])
                         : make_float4(0.f, 0.f, 0.f, 0.f);
            }
            #pragma unroll
            for (int rr = 0; rr < 16; rr++) {
                if (pbuf[rr] >= 0) {
                    float4 vv = vbuf[rr];
                    float s = (vv.x + vv.y) + (vv.z + vv.w);
                    #pragma unroll
                    for (int o = 16; o > 0; o >>= 1) s += __shfl_xor_sync(0xffffffffu, s, o);
                    if (lane == 0) s_cw[(warp + 8 * rr) >> 1][pbuf[rr]] = s;
                }
            }
        }
        __syncthreads();

        // ---- (b1) select decision ----
        if (tid < BB) {
            int b = tid, len = s_len[b];
            int s;
            if (i + 1 >= len) s = -2;
            else if (n == 1) s = 0;
            else {
                float best = -2e9f; int bj = 0;
                for (int j = 0; j < n; j++) {
                    float val = (i + 1 + j < len) ? s_cw[b][j] : -1e9f;
                    if (val > best) { best = val; bj = j; }
                }
                s = bj;
            }
            s_sel[b] = s;
            int merged = -1;
            int2 fr = make_int2(-1, -1);
            if (s >= 0) {
                merged = s_pk[b][s];
                if (i < 62) {
                    if (s >= 1)     fr.x = s - 1;
                    if (s <= n - 2) fr.y = s;
                }
            }
            s_fresh[b] = fr;
            s_nodeidx[b] = (merged >= 0 && i < 62) ? (b * NSLOT + merged) : -1;
            s_rcnt[b] = (fr.x >= 0) + (fr.y >= 0);
        }
        __syncthreads();

        // ---- (b2) parallel shift ----
        {
            unsigned char nvh[16], npk[16];
            float ncw[16];
            #pragma unroll
            for (int t2 = 0; t2 < 16; t2++) {
                int t = tid + 256 * t2;
                int b = t >> 6, j = t & 63;
                int s = s_sel[b];
                if (s >= 0) {
                    unsigned char vh  = s_vh[b][j];
                    unsigned char pk  = s_pk[b][j];
                    float         cw  = s_cw[b][j];
                    unsigned char vh1 = (j < 63) ? s_vh[b][j + 1] : vh;
                    unsigned char pk1 = (j < 63) ? s_pk[b][j + 1] : pk;
                    float         cw1 = (j < 63) ? s_cw[b][j + 1] : cw;
                    nvh[t2] = (j < s) ? vh : ((j == s) ? pk : vh1);
                    bool sh = (j >= s);
                    npk[t2] = sh ? pk1 : pk;
                    ncw[t2] = sh ? cw1 : cw;
                } else { nvh[t2] = 0; npk[t2] = 0; ncw[t2] = 0.f; }
            }
            __syncthreads();
            #pragma unroll
            for (int t2 = 0; t2 < 16; t2++) {
                int t = tid + 256 * t2;
                int b = t >> 6, j = t & 63;
                if (s_sel[b] >= 0) {
                    s_vh[b][j] = nvh[t2];
                    s_pk[b][j] = npk[t2];
                    s_cw[b][j] = ncw[t2];
                }
            }
        }
        __syncthreads();

        // ---- (b3) rows setup ----
        if (tid == 0) {
            int acc = 0;
            for (int b = 0; b < BB; b++) { s_roff[b] = acc; acc += s_rcnt[b]; }
            s_nrows = acc;
        }
        __syncthreads();
        if (tid < BB) {
            int b = tid; int2 fr = s_fresh[b]; int o = s_roff[b];
            if (fr.x >= 0) {
                int p = fr.x;
                s_rows[o] = make_int4(b * NSLOT + s_vh[b][p], b * NSLOT + s_vh[b][p + 1],
                                      b * NSLOT + s_pk[b][p], b * 2 + 0);
                s_rb[o] = (unsigned char)b; s_rln[o] = 0; s_rrn[o] = 1; o++;
            }
            if (fr.y >= 0) {
                int p = fr.y;
                s_rows[o] = make_int4(b * NSLOT + s_vh[b][p], b * NSLOT + s_vh[b][p + 1],
                                      b * NSLOT + s_pk[b][p], b * 2 + 1);
                s_rb[o] = (unsigned char)b; s_rln[o] = 1; s_rrn[o] = 0; o++;
            }
        }
        __syncthreads();

        const int nrows = s_nrows;

        // ---- prefetch epilogue operands ----
        float pvl[2][5], pvr[2][5], clv[2], crv[2];
        #pragma unroll
        for (int r = 0; r < 2; r++) {
            int row = v * 2 + r;
            if (row < nrows) {
                int4 ri = s_rows[row];
                clv[r] = __ldcg(&g_C[ri.x * 512 + hg]);
                crv[r] = __ldcg(&g_C[ri.y * 512 + hg]);
                if (!s_rln[row]) {
                    #pragma unroll
                    for (int g = 0; g < 5; g++)
                        pvl[r][g] = __ldcg(&g_V[(ri.x * 2 + 0) * 2560 + g * 512 + hg]);
                }
                if (!s_rrn[row]) {
                    #pragma unroll
                    for (int g = 0; g < 5; g++)
                        pvr[r][g] = __ldcg(&g_V[(ri.y * 2 + 1) * 2560 + g * 512 + hg]);
                }
            } else { clv[r] = 0.f; crv[r] = 0.f; }
        }

        // ---- (c) vV GEMM for merged nodes ----
        if (i < 62) {
            const int ni = s_nodeidx[v];
            float2 acc[10];
            #pragma unroll
            for (int a = 0; a < 10; a++) acc[a] = make_float2(0.f, 0.f);

            float4 pf[4];
            #pragma unroll
            for (int t = 0; t < 4; t++)
                pf[t] = (ni >= 0)
                      ? __ldcg((const float4*)&g_H[ni * 512 + (u + 4 * t) * 4])
                      : make_float4(0.f, 0.f, 0.f, 0.f);
            #pragma unroll
            for (int t = 0; t < 4; t++)
                ((float4*)(Asb0 + v * A_STRIDE))[u + 4 * t] = pf[t];
            __syncthreads();

            for (int c = 0; c < 8; c++) {
                if (c < 7) {
                    #pragma unroll
                    for (int t = 0; t < 4; t++)
                        pf[t] = (ni >= 0)
                              ? __ldcg((const float4*)&g_H[ni * 512 + (c + 1) * 64 + (u + 4 * t) * 4])
                              : make_float4(0.f, 0.f, 0.f, 0.f);
                }
                const float* A = (c & 1) ? Asb1 : Asb0;
                if (ni >= 0) {
                    #pragma unroll
                    for (int k4 = 0; k4 < 16; k4++) {
                        float4 av = ((const float4*)(A + v * A_STRIDE))[k4];
                        float2 alo = make_float2(av.x, av.y);
                        float2 ahi = make_float2(av.z, av.w);
                        #pragma unroll
                        for (int a = 0; a < 10; a++) {
                            int r2 = (a >= 5 ? 20 : 0) + (a % 5) * 4 + u;
                            float4 wv = ((const float4*)(Wres + r2 * W_STRIDE))[c * 16 + k4];
                            ffma2(acc[a], alo, make_float2(wv.x, wv.y));
                            ffma2(acc[a], ahi, make_float2(wv.z, wv.w));
                        }
                    }
                }
                if (c < 7) {
                    float* An = (c & 1) ? Asb0 : Asb1;
                    #pragma unroll
                    for (int t = 0; t < 4; t++)
                        ((float4*)(An + v * A_STRIDE))[u + 4 * t] = pf[t];
                }
                __syncthreads();
            }

            if (ni >= 0) {
                #pragma unroll
                for (int a = 0; a < 10; a++) {
                    int side = (a >= 5), g = a % 5;
                    float val = acc[a].x + acc[a].y;
                    sVnew[v * 40 + side * 20 + g * 4 + u] = val;
                    g_V[(ni * 2 + side) * 2560 + g * 512 + hg] = val;
                }
            }
            __syncthreads();
        }

        // ---- (d) epilogue ----
        if (nrows > 0) {
            float* cwdst = g_cwp[(i + 1) & 1];
            #pragma unroll
            for (int r = 0; r < 2; r++) {
                int row = v * 2 + r;
                float p = 0.f;
                if (row < nrows) {
                    int bb = s_rb[row];
                    float vg[5];
                    #pragma unroll
                    for (int g = 0; g < 5; g++) {
                        float L = s_rln[row] ? sVnew[bb * 40 + g * 4 + u]      : pvl[r][g];
                        float R = s_rrn[row] ? sVnew[bb * 40 + 20 + g * 4 + u] : pvr[r][g];
                        vg[g] = L + R;
                    }
                    float cn = clv[r] * sigm(vg[1] + bfl + 1.f) + crv[r] * sigm(vg[2] + bfr + 1.f)
                             + tanhf(vg[3] + bu) * sigm(vg[0] + bi);
                    float hn = sigm(vg[4] + bo) * tanhf(cn);
                    int nst = s_rows[row].z;
                    g_H[nst * 512 + hg] = hn;
                    g_C[nst * 512 + hg] = cn;
                    p = hn * qv;
                }
                p += __shfl_xor_sync(0xffffffffu, p, 1);
                p += __shfl_xor_sync(0xffffffffu, p, 2);
                if (row < nrows && u == 0) cwdst[s_rows[row].w * 128 + blk] = p;
            }
        }
        target += GRID; grid_barrier(target);
    }

    // ---- output ----
    if (blk < BB) {
        int base = (blk * NSLOT + s_vh[blk][0]) * 512;
        out[blk * 512 + tid]                  = __ldcg(&g_H[base + tid]);
        out[blk * 512 + 256 + tid]            = __ldcg(&g_H[base + 256 + tid]);
        out[BB * 512 + blk * 512 + tid]       = __ldcg(&g_C[base + tid]);
        out[BB * 512 + blk * 512 + 256 + tid] = __ldcg(&g_C[base + 256 + tid]);
    }
}

// ---------------------------------------------------------------------------
extern "C" void kernel_launch(void* const* d_in, const int* in_sizes, int n_in,
                              void* d_out, int out_size)
{
    const float* x      = (const float*)d_in[0];
    const int*   length = (const int*)  d_in[1];
    const float* w_word = (const float*)d_in[2];
    const float* b_word = (const float*)d_in[3];
    const float* w_comp = (const float*)d_in[4];
    const float* b_comp = (const float*)d_in[5];
    const float* q      = (const float*)d_in[6];
    float* out = (float*)d_out;

    static int smem_set = 0;
    if (!smem_set) {
        cudaFuncSetAttribute(tree_loop, cudaFuncAttributeMaxDynamicSharedMemorySize,
                             SMEM_BYTES);
        cudaFuncSetAttribute(vv_full, cudaFuncAttributeMaxDynamicSharedMemorySize,
                             VV_SMEM);
        smem_set = 1;
    }

    word_gemm<<<dim3(16, 64), 256>>>(x, w_word, b_word);
    vv_full<<<GRID, 256, VV_SMEM>>>(w_comp);
    pair_epi<<<4032, 256>>>(b_comp, q);
    tree_loop<<<GRID, TPB, SMEM_BYTES>>>(length, q, w_comp, b_comp, out);
}

// round 11
// speedup vs baseline: 1.0248x; 1.0248x over previous
#include <cuda_runtime.h>
#include <math.h>

#define BB 64
#define GRID 128
#define TPB 256
#define NSLOT 128
#define NST (BB*NSLOT*512)

__device__ float g_H[NST];
__device__ float g_C[NST];
// vV cache: [b][slot][side][2560] ; side0 = W_l@h, side1 = W_r@h
__device__ float g_V[BB*NSLOT*2*2560];
__device__ float g_cwp[2][128*128];   // cw partials, parity double-buffered
__device__ float g_cw0[BB*63];
__device__ unsigned g_bar[4];

__device__ __forceinline__ float sigm(float x){ return 1.0f/(1.0f+expf(-x)); }

__device__ __forceinline__ void ffma2(float2 &acc, float2 a, float2 b){
    asm("fma.rn.f32x2 %0, %1, %2, %0;"
        : "+l"(reinterpret_cast<unsigned long long&>(acc))
        : "l"(reinterpret_cast<unsigned long long&>(a)),
          "l"(reinterpret_cast<unsigned long long&>(b)));
}

__device__ __forceinline__ void grid_barrier(unsigned target){
    __syncthreads();
    if (threadIdx.x == 0){
        asm volatile("red.release.gpu.global.add.u32 [%0], 1;"
                     :: "l"(&g_bar[blockIdx.x & 3]) : "memory");
        unsigned v0, v1, v2, v3;
        do {
            asm volatile("ld.acquire.gpu.global.u32 %0, [%1];" : "=r"(v0) : "l"(&g_bar[0]) : "memory");
            asm volatile("ld.acquire.gpu.global.u32 %0, [%1];" : "=r"(v1) : "l"(&g_bar[1]) : "memory");
            asm volatile("ld.acquire.gpu.global.u32 %0, [%1];" : "=r"(v2) : "l"(&g_bar[2]) : "memory");
            asm volatile("ld.acquire.gpu.global.u32 %0, [%1];" : "=r"(v3) : "l"(&g_bar[3]) : "memory");
        } while (v0 + v1 + v2 + v3 < target);
    }
    __syncthreads();
}

// ---------------------------------------------------------------------------
// Word GEMM (f32x2, transposed W tile); also zeroes the grid-barrier counters
// ---------------------------------------------------------------------------
__global__ __launch_bounds__(256) void word_gemm(
    const float* __restrict__ x, const float* __restrict__ w,
    const float* __restrict__ bias)
{
    if (blockIdx.x == 0 && blockIdx.y == 0 && threadIdx.x < 4)
        g_bar[threadIdx.x] = 0u;

    __shared__ float As[64][33];
    __shared__ float Wt[32][68];
    int tid = threadIdx.x;
    int tx = tid & 15, ty = tid >> 4;
    int m0 = blockIdx.y * 64;
    int c0 = blockIdx.x * 64;
    const int lr = tid >> 5, kkld = tid & 31;

    float2 acc[4][2];
    #pragma unroll
    for (int r = 0; r < 4; r++){ acc[r][0] = make_float2(0.f,0.f); acc[r][1] = make_float2(0.f,0.f); }

    for (int k0 = 0; k0 < 512; k0 += 32) {
        #pragma unroll
        for (int t = 0; t < 8; t++) {
            int r = lr + 8 * t;
            As[r][kkld] = x[(m0 + r) * 512 + k0 + kkld];
            Wt[kkld][r] = w[(c0 + r) * 512 + k0 + kkld];
        }
        __syncthreads();
        #pragma unroll
        for (int kk = 0; kk < 32; kk++) {
            float4 wv = *(const float4*)&Wt[kk][tx * 4];
            #pragma unroll
            for (int r = 0; r < 4; r++) {
                float a = As[ty * 4 + r][kk];
                ffma2(acc[r][0], make_float2(a, a), make_float2(wv.x, wv.y));
                ffma2(acc[r][1], make_float2(a, a), make_float2(wv.z, wv.w));
            }
        }
        __syncthreads();
    }
    #pragma unroll
    for (int r = 0; r < 4; r++) {
        int m = m0 + ty * 4 + r;
        int b = m >> 6, leaf = m & 63;
        int base = (b * NSLOT + leaf) * 512;
        #pragma unroll
        for (int c2 = 0; c2 < 2; c2++) {
            #pragma unroll
            for (int e = 0; e < 2; e++) {
                int col = c0 + tx * 4 + c2 * 2 + e;
                float v = (e ? acc[r][c2].y : acc[r][c2].x) + bias[col];
                if (col < 512) g_H[base + col] = v;
                else           g_C[base + col - 512] = v;
            }
        }
    }
}

// ---------------------------------------------------------------------------
// vV for all 4096 leaf nodes (round-9 grid version, float4 smem reads)
// ---------------------------------------------------------------------------
__global__ __launch_bounds__(256) void vv_full(const float* __restrict__ wcomp)
{
    __shared__ float As[128][36];
    __shared__ float Ws[5][8][36];
    const int tid = threadIdx.x;
    const int tx = tid & 7, ty = tid >> 3;
    const int side = blockIdx.x & 1;
    const int h0 = (blockIdx.x >> 1) * 8;
    const int m0 = blockIdx.y * 128;

    const int lr = tid >> 5, kkld = tid & 31;
    int abase[16];
    #pragma unroll
    for (int t = 0; t < 16; t++) {
        int row = m0 + lr + 8 * t;
        int b = row >> 6, leaf = row & 63;
        abase[t] = (b * NSLOT + leaf) * 512;
    }

    float2 acc[4][5];
    #pragma unroll
    for (int r = 0; r < 4; r++)
        #pragma unroll
        for (int g = 0; g < 5; g++) acc[r][g] = make_float2(0.f, 0.f);

    for (int k0 = 0; k0 < 512; k0 += 32) {
        #pragma unroll
        for (int t = 0; t < 16; t++)
            As[lr + 8 * t][kkld] = g_H[abase[t] + k0 + kkld];
        #pragma unroll
        for (int t = 0; t < 5; t++) {
            int idx = tid + 256 * t;
            int g = idx >> 8, rem = idx & 255, hh = rem >> 5, kk = rem & 31;
            Ws[g][hh][kk] = wcomp[(g * 512 + h0 + hh) * 1024 + side * 512 + k0 + kk];
        }
        __syncthreads();
        #pragma unroll
        for (int k4 = 0; k4 < 8; k4++) {
            float4 wv[5];
            #pragma unroll
            for (int g = 0; g < 5; g++) wv[g] = ((const float4*)Ws[g][tx])[k4];
            #pragma unroll
            for (int r = 0; r < 4; r++) {
                float4 av = ((const float4*)As[ty * 4 + r])[k4];
                #pragma unroll
                for (int g = 0; g < 5; g++) {
                    ffma2(acc[r][g], make_float2(av.x, av.y), make_float2(wv[g].x, wv[g].y));
                    ffma2(acc[r][g], make_float2(av.z, av.w), make_float2(wv[g].z, wv[g].w));
                }
            }
        }
        __syncthreads();
    }

    #pragma unroll
    for (int r = 0; r < 4; r++) {
        int row = m0 + ty * 4 + r;
        int b = row >> 6, leaf = row & 63;
        int vbase = ((b * NSLOT + leaf) * 2 + side) * 2560;
        #pragma unroll
        for (int g = 0; g < 5; g++)
            g_V[vbase + g * 512 + h0 + tx] = acc[r][g].x + acc[r][g].y;
    }
}

// ---------------------------------------------------------------------------
// Iter-0 candidates from vV: h/c + cw0.  4032 blocks.
// ---------------------------------------------------------------------------
__global__ __launch_bounds__(256) void pair_epi(
    const float* __restrict__ bcomp, const float* __restrict__ q)
{
    __shared__ float red[8];
    int pb = blockIdx.x;
    int b = pb / 63, j = pb - b * 63;
    int nl = b * NSLOT + j, nr = nl + 1, ns = b * NSLOT + 64 + j;
    int tid = threadIdx.x, lane = tid & 31, warp = tid >> 5;
    float p = 0.f;
    #pragma unroll
    for (int half = 0; half < 2; half++) {
        int hd = tid + 256 * half;
        float vg[5];
        #pragma unroll
        for (int g = 0; g < 5; g++)
            vg[g] = __ldcg(&g_V[(nl * 2 + 0) * 2560 + g * 512 + hd])
                  + __ldcg(&g_V[(nr * 2 + 1) * 2560 + g * 512 + hd])
                  + bcomp[g * 512 + hd];
        float cl = __ldcg(&g_C[nl * 512 + hd]), cr = __ldcg(&g_C[nr * 512 + hd]);
        float cn = cl * sigm(vg[1] + 1.f) + cr * sigm(vg[2] + 1.f)
                 + tanhf(vg[3]) * sigm(vg[0]);
        float hn = sigm(vg[4]) * tanhf(cn);
        g_H[ns * 512 + hd] = hn;
        g_C[ns * 512 + hd] = cn;
        p += hn * q[hd];
    }
    #pragma unroll
    for (int o = 16; o > 0; o >>= 1) p += __shfl_xor_sync(0xffffffffu, p, o);
    if (lane == 0) red[warp] = p;
    __syncthreads();
    if (tid == 0) {
        float s = 0.f;
        #pragma unroll
        for (int w = 0; w < 8; w++) s += red[w];
        g_cw0[b * 63 + j] = s;
    }
}

// ---------------------------------------------------------------------------
// Persistent loop (low register pressure: smem ping-pong state, batched fold)
// ---------------------------------------------------------------------------
#define W_STRIDE 516
#define A_STRIDE 68
#define WRES_F   (40*W_STRIDE)
#define ASB_F    (64*A_STRIDE)
#define SVN_F    (64*40)
#define SMEM_BYTES ((WRES_F + 2*ASB_F + SVN_F)*4)

__global__ __launch_bounds__(TPB, 1) void tree_loop(
    const int* __restrict__ length, const float* __restrict__ q,
    const float* __restrict__ wcomp, const float* __restrict__ bcomp,
    float* __restrict__ out)
{
    extern __shared__ float smem[];
    float* Wres  = smem;
    float* Asb0  = smem + WRES_F;
    float* Asb1  = smem + WRES_F + ASB_F;
    float* sVnew = smem + WRES_F + 2*ASB_F;

    __shared__ unsigned char s_vh[2][BB][64];   // ping-pong by iter parity
    __shared__ unsigned char s_pk[2][BB][64];
    __shared__ float s_cw[2][BB][64];
    __shared__ int2  s_fresh[BB];
    __shared__ int   s_sel[BB];
    __shared__ int   s_nodeidx[BB];
    __shared__ int4  s_rows[128];
    __shared__ unsigned char s_rb[128], s_rln[128], s_rrn[128];
    __shared__ int   s_rcnt[BB], s_roff[BB], s_len[BB];
    __shared__ int   s_nrows, s_maxlen;

    const int tid = threadIdx.x, blk = blockIdx.x;
    const int u = tid & 3, v = tid >> 2;
    const int lane = tid & 31, warp = tid >> 5;
    const int hg = blk * 4 + u;

    for (int idx = tid; idx < 40 * 512; idx += TPB) {
        int r2 = idx >> 9, k = idx & 511;
        int side = r2 / 20, rem = r2 % 20, g = rem >> 2, hgo = rem & 3;
        Wres[r2 * W_STRIDE + k] = wcomp[(g * 512 + blk * 4 + hgo) * 1024 + side * 512 + k];
    }
    const float qv  = q[hg];
    const float bi  = bcomp[hg],        bfl = bcomp[512 + hg], bfr = bcomp[1024 + hg];
    const float bu  = bcomp[1536 + hg], bo  = bcomp[2048 + hg];

    for (int t = tid; t < BB * 64; t += TPB) {
        int b = t >> 6, j = t & 63;
        s_vh[0][b][j] = (unsigned char)j;
        s_pk[0][b][j] = (unsigned char)(64 + j);
        s_cw[0][b][j] = (j < 63) ? __ldcg(&g_cw0[b * 63 + j]) : -1e9f;
    }
    if (tid < BB) { s_len[tid] = length[tid]; s_fresh[tid] = make_int2(-1, -1); }
    __syncthreads();
    if (tid == 0) {
        int m = 0;
        for (int b = 0; b < BB; b++) if (s_len[b] > m) m = s_len[b];
        s_maxlen = m;
    }
    __syncthreads();
    const int maxlen = s_maxlen;

    unsigned target = 0;
    int fin = 0;                              // buffer holding final state

    for (int i = 0; i < 63; i++) {
        if (i + 1 >= maxlen) break;
        const int n = 63 - i;
        const int cur = i & 1, nxt = cur ^ 1;
        fin = nxt;

        // ---- (a) fold cw partials, 2 batches of 8 rids/warp ----
        if (i > 0) {
            const float* cwsrc = g_cwp[i & 1];
            #pragma unroll
            for (int half = 0; half < 2; half++) {
                float4 vbuf[8];
                int    pbuf[8];
                #pragma unroll
                for (int rr = 0; rr < 8; rr++) {
                    int rid = warp + 8 * (half * 8 + rr);
                    int b = rid >> 1;
                    int2 fr = s_fresh[b];
                    int pidx = (rid & 1) ? fr.y : fr.x;
                    pbuf[rr] = pidx;
                    vbuf[rr] = (pidx >= 0)
                             ? __ldcg((const float4*)&cwsrc[rid * 128 + lane * 4])
                             : make_float4(0.f, 0.f, 0.f, 0.f);
                }
                #pragma unroll
                for (int rr = 0; rr < 8; rr++) {
                    if (pbuf[rr] >= 0) {
                        float4 vv = vbuf[rr];
                        float s = (vv.x + vv.y) + (vv.z + vv.w);
                        #pragma unroll
                        for (int o = 16; o > 0; o >>= 1) s += __shfl_xor_sync(0xffffffffu, s, o);
                        if (lane == 0) s_cw[cur][(warp + 8 * (half * 8 + rr)) >> 1][pbuf[rr]] = s;
                    }
                }
            }
        }
        __syncthreads();

        // ---- (b1) select decision ----
        if (tid < BB) {
            int b = tid, len = s_len[b];
            int s;
            if (i + 1 >= len) s = -2;
            else if (n == 1) s = 0;
            else {
                float best = -2e9f; int bj = 0;
                for (int j = 0; j < n; j++) {
                    float val = (i + 1 + j < len) ? s_cw[cur][b][j] : -1e9f;
                    if (val > best) { best = val; bj = j; }
                }
                s = bj;
            }
            s_sel[b] = s;
            int merged = -1;
            int2 fr = make_int2(-1, -1);
            if (s >= 0) {
                merged = s_pk[cur][b][s];
                if (i < 62) {
                    if (s >= 1)     fr.x = s - 1;
                    if (s <= n - 2) fr.y = s;
                }
            }
            s_fresh[b] = fr;
            s_nodeidx[b] = (merged >= 0 && i < 62) ? (b * NSLOT + merged) : -1;
            s_rcnt[b] = (fr.x >= 0) + (fr.y >= 0);
        }
        __syncthreads();

        // ---- (b2) shift cur -> nxt (smem ping-pong, no reg buffering) ----
        #pragma unroll
        for (int t2 = 0; t2 < 16; t2++) {
            int t = tid + 256 * t2;
            int b = t >> 6, j = t & 63;
            int s = s_sel[b];
            if (s >= 0) {
                int j1 = (j < 63) ? j + 1 : j;
                s_vh[nxt][b][j] = (j < s) ? s_vh[cur][b][j]
                               : ((j == s) ? s_pk[cur][b][j] : s_vh[cur][b][j1]);
                bool sh = (j >= s);
                s_pk[nxt][b][j] = s_pk[cur][b][sh ? j1 : j];
                s_cw[nxt][b][j] = s_cw[cur][b][sh ? j1 : j];
            } else {
                s_vh[nxt][b][j] = s_vh[cur][b][j];
                s_pk[nxt][b][j] = s_pk[cur][b][j];
                s_cw[nxt][b][j] = s_cw[cur][b][j];
            }
        }
        __syncthreads();

        // ---- (b3) rows setup (post-shift state = nxt) ----
        if (tid == 0) {
            int acc = 0;
            for (int b = 0; b < BB; b++) { s_roff[b] = acc; acc += s_rcnt[b]; }
            s_nrows = acc;
        }
        __syncthreads();
        if (tid < BB) {
            int b = tid; int2 fr = s_fresh[b]; int o = s_roff[b];
            if (fr.x >= 0) {
                int p = fr.x;
                s_rows[o] = make_int4(b * NSLOT + s_vh[nxt][b][p], b * NSLOT + s_vh[nxt][b][p + 1],
                                      b * NSLOT + s_pk[nxt][b][p], b * 2 + 0);
                s_rb[o] = (unsigned char)b; s_rln[o] = 0; s_rrn[o] = 1; o++;
            }
            if (fr.y >= 0) {
                int p = fr.y;
                s_rows[o] = make_int4(b * NSLOT + s_vh[nxt][b][p], b * NSLOT + s_vh[nxt][b][p + 1],
                                      b * NSLOT + s_pk[nxt][b][p], b * 2 + 1);
                s_rb[o] = (unsigned char)b; s_rln[o] = 1; s_rrn[o] = 0; o++;
            }
        }
        __syncthreads();

        const int nrows = s_nrows;

        // ---- prefetch epilogue operands (hidden under GEMM) ----
        float pvl[2][5], pvr[2][5], clv[2], crv[2];
        #pragma unroll
        for (int r = 0; r < 2; r++) {
            int row = v * 2 + r;
            if (row < nrows) {
                int4 ri = s_rows[row];
                clv[r] = __ldcg(&g_C[ri.x * 512 + hg]);
                crv[r] = __ldcg(&g_C[ri.y * 512 + hg]);
                if (!s_rln[row]) {
                    #pragma unroll
                    for (int g = 0; g < 5; g++)
                        pvl[r][g] = __ldcg(&g_V[(ri.x * 2 + 0) * 2560 + g * 512 + hg]);
                }
                if (!s_rrn[row]) {
                    #pragma unroll
                    for (int g = 0; g < 5; g++)
                        pvr[r][g] = __ldcg(&g_V[(ri.y * 2 + 1) * 2560 + g * 512 + hg]);
                }
            } else { clv[r] = 0.f; crv[r] = 0.f; }
        }

        // ---- (c) vV GEMM for merged nodes: M=64, K=512, 40 outs/block ----
        if (i < 62) {
            const int ni = s_nodeidx[v];
            float2 acc[10];
            #pragma unroll
            for (int a = 0; a < 10; a++) acc[a] = make_float2(0.f, 0.f);

            float4 pf[4];
            #pragma unroll
            for (int t = 0; t < 4; t++)
                pf[t] = (ni >= 0)
                      ? __ldcg((const float4*)&g_H[ni * 512 + (u + 4 * t) * 4])
                      : make_float4(0.f, 0.f, 0.f, 0.f);
            #pragma unroll
            for (int t = 0; t < 4; t++)
                ((float4*)(Asb0 + v * A_STRIDE))[u + 4 * t] = pf[t];
            __syncthreads();

            for (int c = 0; c < 8; c++) {
                if (c < 7) {
                    #pragma unroll
                    for (int t = 0; t < 4; t++)
                        pf[t] = (ni >= 0)
                              ? __ldcg((const float4*)&g_H[ni * 512 + (c + 1) * 64 + (u + 4 * t) * 4])
                              : make_float4(0.f, 0.f, 0.f, 0.f);
                }
                const float* A = (c & 1) ? Asb1 : Asb0;
                if (ni >= 0) {
                    #pragma unroll
                    for (int k4 = 0; k4 < 16; k4++) {
                        float4 av = ((const float4*)(A + v * A_STRIDE))[k4];
                        float2 alo = make_float2(av.x, av.y);
                        float2 ahi = make_float2(av.z, av.w);
                        #pragma unroll
                        for (int a = 0; a < 10; a++) {
                            int r2 = (a >= 5 ? 20 : 0) + (a % 5) * 4 + u;
                            float4 wv = ((const float4*)(Wres + r2 * W_STRIDE))[c * 16 + k4];
                            ffma2(acc[a], alo, make_float2(wv.x, wv.y));
                            ffma2(acc[a], ahi, make_float2(wv.z, wv.w));
                        }
                    }
                }
                if (c < 7) {
                    float* An = (c & 1) ? Asb0 : Asb1;
                    #pragma unroll
                    for (int t = 0; t < 4; t++)
                        ((float4*)(An + v * A_STRIDE))[u + 4 * t] = pf[t];
                }
                __syncthreads();
            }

            if (ni >= 0) {
                #pragma unroll
                for (int a = 0; a < 10; a++) {
                    int side = (a >= 5), g = a % 5;
                    float val = acc[a].x + acc[a].y;
                    sVnew[v * 40 + side * 20 + g * 4 + u] = val;
                    g_V[(ni * 2 + side) * 2560 + g * 512 + hg] = val;
                }
            }
            __syncthreads();
        }

        // ---- (d) epilogue ----
        if (nrows > 0) {
            float* cwdst = g_cwp[(i + 1) & 1];
            #pragma unroll
            for (int r = 0; r < 2; r++) {
                int row = v * 2 + r;
                float p = 0.f;
                if (row < nrows) {
                    int bb = s_rb[row];
                    float vg[5];
                    #pragma unroll
                    for (int g = 0; g < 5; g++) {
                        float L = s_rln[row] ? sVnew[bb * 40 + g * 4 + u]      : pvl[r][g];
                        float R = s_rrn[row] ? sVnew[bb * 40 + 20 + g * 4 + u] : pvr[r][g];
                        vg[g] = L + R;
                    }
                    float cn = clv[r] * sigm(vg[1] + bfl + 1.f) + crv[r] * sigm(vg[2] + bfr + 1.f)
                             + tanhf(vg[3] + bu) * sigm(vg[0] + bi);
                    float hn = sigm(vg[4] + bo) * tanhf(cn);
                    int nst = s_rows[row].z;
                    g_H[nst * 512 + hg] = hn;
                    g_C[nst * 512 + hg] = cn;
                    p = hn * qv;
                }
                p += __shfl_xor_sync(0xffffffffu, p, 1);
                p += __shfl_xor_sync(0xffffffffu, p, 2);
                if (row < nrows && u == 0) cwdst[s_rows[row].w * 128 + blk] = p;
            }
        }
        target += GRID; grid_barrier(target);
    }

    // ---- output ----
    if (blk < BB) {
        int base = (blk * NSLOT + s_vh[fin][blk][0]) * 512;
        out[blk * 512 + tid]                  = __ldcg(&g_H[base + tid]);
        out[blk * 512 + 256 + tid]            = __ldcg(&g_H[base + 256 + tid]);
        out[BB * 512 + blk * 512 + tid]       = __ldcg(&g_C[base + tid]);
        out[BB * 512 + blk * 512 + 256 + tid] = __ldcg(&g_C[base + 256 + tid]);
    }
}

// ---------------------------------------------------------------------------
extern "C" void kernel_launch(void* const* d_in, const int* in_sizes, int n_in,
                              void* d_out, int out_size)
{
    const float* x      = (const float*)d_in[0];
    const int*   length = (const int*)  d_in[1];
    const float* w_word = (const float*)d_in[2];
    const float* b_word = (const float*)d_in[3];
    const float* w_comp = (const float*)d_in[4];
    const float* b_comp = (const float*)d_in[5];
    const float* q      = (const float*)d_in[6];
    float* out = (float*)d_out;

    static int smem_set = 0;
    if (!smem_set) {
        cudaFuncSetAttribute(tree_loop, cudaFuncAttributeMaxDynamicSharedMemorySize,
                             SMEM_BYTES);
        smem_set = 1;
    }

    word_gemm<<<dim3(16, 64), 256>>>(x, w_word, b_word);
    vv_full<<<dim3(128, 32), 256>>>(w_comp);
    pair_epi<<<4032, 256>>>(b_comp, q);
    tree_loop<<<GRID, TPB, SMEM_BYTES>>>(length, q, w_comp, b_comp, out);
}

// round 13
// speedup vs baseline: 1.0600x; 1.0344x over previous
#include <cuda_runtime.h>
#include <cstdint>
#include <math.h>

#define BB 64
#define GRID 128
#define TPB 256
#define NSLOT 128
#define NST (BB*NSLOT*512)

__device__ float g_H[NST];
__device__ float g_C[NST];
// vV cache: [b][slot][side][2560] ; side0 = W_l@h, side1 = W_r@h
__device__ float g_V[BB*NSLOT*2*2560];
__device__ float g_cwp[2][128*128];   // cw partials, parity double-buffered
__device__ float g_cw0[BB*63];
__device__ unsigned g_bar[4];

__device__ __forceinline__ float sigm(float x){ return 1.0f/(1.0f+expf(-x)); }

__device__ __forceinline__ void ffma2(float2 &acc, float2 a, float2 b){
    asm("fma.rn.f32x2 %0, %1, %2, %0;"
        : "+l"(reinterpret_cast<unsigned long long&>(acc))
        : "l"(reinterpret_cast<unsigned long long&>(a)),
          "l"(reinterpret_cast<unsigned long long&>(b)));
}

__device__ __forceinline__ void cp16(unsigned s, const void* g){
    asm volatile("cp.async.ca.shared.global [%0], [%1], 16;\n" :: "r"(s), "l"(g));
}

__device__ __forceinline__ void grid_barrier(unsigned target){
    __syncthreads();
    if (threadIdx.x == 0){
        asm volatile("red.release.gpu.global.add.u32 [%0], 1;"
                     :: "l"(&g_bar[blockIdx.x & 3]) : "memory");
        unsigned v0, v1, v2, v3;
        do {
            asm volatile("ld.acquire.gpu.global.u32 %0, [%1];" : "=r"(v0) : "l"(&g_bar[0]) : "memory");
            asm volatile("ld.acquire.gpu.global.u32 %0, [%1];" : "=r"(v1) : "l"(&g_bar[1]) : "memory");
            asm volatile("ld.acquire.gpu.global.u32 %0, [%1];" : "=r"(v2) : "l"(&g_bar[2]) : "memory");
            asm volatile("ld.acquire.gpu.global.u32 %0, [%1];" : "=r"(v3) : "l"(&g_bar[3]) : "memory");
        } while (v0 + v1 + v2 + v3 < target);
    }
    __syncthreads();
}

// ---------------------------------------------------------------------------
// Word GEMM (f32x2, transposed W tile); also zeroes the grid-barrier counters
// ---------------------------------------------------------------------------
__global__ __launch_bounds__(256) void word_gemm(
    const float* __restrict__ x, const float* __restrict__ w,
    const float* __restrict__ bias)
{
    if (blockIdx.x == 0 && blockIdx.y == 0 && threadIdx.x < 4)
        g_bar[threadIdx.x] = 0u;

    __shared__ float As[64][33];
    __shared__ float Wt[32][68];
    int tid = threadIdx.x;
    int tx = tid & 15, ty = tid >> 4;
    int m0 = blockIdx.y * 64;
    int c0 = blockIdx.x * 64;
    const int lr = tid >> 5, kkld = tid & 31;

    float2 acc[4][2];
    #pragma unroll
    for (int r = 0; r < 4; r++){ acc[r][0] = make_float2(0.f,0.f); acc[r][1] = make_float2(0.f,0.f); }

    for (int k0 = 0; k0 < 512; k0 += 32) {
        #pragma unroll
        for (int t = 0; t < 8; t++) {
            int r = lr + 8 * t;
            As[r][kkld] = x[(m0 + r) * 512 + k0 + kkld];
            Wt[kkld][r] = w[(c0 + r) * 512 + k0 + kkld];
        }
        __syncthreads();
        #pragma unroll
        for (int kk = 0; kk < 32; kk++) {
            float4 wv = *(const float4*)&Wt[kk][tx * 4];
            #pragma unroll
            for (int r = 0; r < 4; r++) {
                float a = As[ty * 4 + r][kk];
                ffma2(acc[r][0], make_float2(a, a), make_float2(wv.x, wv.y));
                ffma2(acc[r][1], make_float2(a, a), make_float2(wv.z, wv.w));
            }
        }
        __syncthreads();
    }
    #pragma unroll
    for (int r = 0; r < 4; r++) {
        int m = m0 + ty * 4 + r;
        int b = m >> 6, leaf = m & 63;
        int base = (b * NSLOT + leaf) * 512;
        #pragma unroll
        for (int c2 = 0; c2 < 2; c2++) {
            #pragma unroll
            for (int e = 0; e < 2; e++) {
                int col = c0 + tx * 4 + c2 * 2 + e;
                float v = (e ? acc[r][c2].y : acc[r][c2].x) + bias[col];
                if (col < 512) g_H[base + col] = v;
                else           g_C[base + col - 512] = v;
            }
        }
    }
}

// ---------------------------------------------------------------------------
// vV for all 4096 leaf nodes: cp.async double-buffered, 2 blocks/SM
// grid: x = 64 hgroups * 2 sides, y = 32 row-tiles of 128
// ---------------------------------------------------------------------------
__global__ __launch_bounds__(256) void vv_full(const float* __restrict__ wcomp)
{
    __shared__ float As[2][128*36];
    __shared__ float Ws[2][40*36];
    const int tid = threadIdx.x;
    const int tx = tid & 7, ty = tid >> 3;
    const int side = blockIdx.x & 1;
    const int h0 = (blockIdx.x >> 1) * 8;
    const int m0 = blockIdx.y * 128;

    // As fill roles: 128 rows x 8 quads = 1024 float4 / 256 thr = 4 each
    int arow[4], aq[4];
    const float* asrc[4];
    #pragma unroll
    for (int ii = 0; ii < 4; ii++) {
        int f = tid + 256 * ii; int row = f >> 3; int qd = f & 7;
        arow[ii] = row; aq[ii] = qd;
        int rg = m0 + row; int b = rg >> 6, leaf = rg & 63;
        asrc[ii] = &g_H[(b * NSLOT + leaf) * 512 + qd * 4];
    }
    // Ws fill roles: 40 rows x 8 quads = 320 float4
    int wrow[2], wq[2]; bool wok[2];
    const float* wsrc[2];
    #pragma unroll
    for (int tt = 0; tt < 2; tt++) {
        int f = tid + 256 * tt; wok[tt] = (f < 320);
        int r2 = f >> 3, qd = f & 7;
        wrow[tt] = r2; wq[tt] = qd;
        int g = r2 >> 3, hh = r2 & 7;
        wsrc[tt] = wok[tt]
                 ? &wcomp[(g * 512 + h0 + hh) * 1024 + side * 512 + qd * 4]
                 : wcomp;
    }

    float2 acc[4][5];
    #pragma unroll
    for (int r = 0; r < 4; r++)
        #pragma unroll
        for (int g = 0; g < 5; g++) acc[r][g] = make_float2(0.f, 0.f);

    // issue chunk 0 -> buf 0
    {
        #pragma unroll
        for (int ii = 0; ii < 4; ii++)
            cp16((unsigned)__cvta_generic_to_shared(&As[0][arow[ii]*36 + aq[ii]*4]), asrc[ii]);
        #pragma unroll
        for (int tt = 0; tt < 2; tt++)
            if (wok[tt])
                cp16((unsigned)__cvta_generic_to_shared(&Ws[0][wrow[tt]*36 + wq[tt]*4]), wsrc[tt]);
        asm volatile("cp.async.commit_group;\n");
    }

    for (int c = 0; c < 16; c++) {
        if (c < 15) {
            int koff = (c + 1) * 32;
            int buf = (c + 1) & 1;
            #pragma unroll
            for (int ii = 0; ii < 4; ii++)
                cp16((unsigned)__cvta_generic_to_shared(&As[buf][arow[ii]*36 + aq[ii]*4]), asrc[ii] + koff);
            #pragma unroll
            for (int tt = 0; tt < 2; tt++)
                if (wok[tt])
                    cp16((unsigned)__cvta_generic_to_shared(&Ws[buf][wrow[tt]*36 + wq[tt]*4]), wsrc[tt] + koff);
            asm volatile("cp.async.commit_group;\n");
            asm volatile("cp.async.wait_group 1;\n");
        } else {
            asm volatile("cp.async.wait_group 0;\n");
        }
        __syncthreads();
        const float* A = As[c & 1];
        const float* W = Ws[c & 1];
        #pragma unroll
        for (int k4 = 0; k4 < 8; k4++) {
            float4 wv[5];
            #pragma unroll
            for (int g = 0; g < 5; g++)
                wv[g] = ((const float4*)(W + (g * 8 + tx) * 36))[k4];
            #pragma unroll
            for (int r = 0; r < 4; r++) {
                float4 av = ((const float4*)(A + (ty * 4 + r) * 36))[k4];
                #pragma unroll
                for (int g = 0; g < 5; g++) {
                    ffma2(acc[r][g], make_float2(av.x, av.y), make_float2(wv[g].x, wv[g].y));
                    ffma2(acc[r][g], make_float2(av.z, av.w), make_float2(wv[g].z, wv[g].w));
                }
            }
        }
        __syncthreads();
    }

    #pragma unroll
    for (int r = 0; r < 4; r++) {
        int row = m0 + ty * 4 + r;
        int b = row >> 6, leaf = row & 63;
        int vbase = ((b * NSLOT + leaf) * 2 + side) * 2560;
        #pragma unroll
        for (int g = 0; g < 5; g++)
            g_V[vbase + g * 512 + h0 + tx] = acc[r][g].x + acc[r][g].y;
    }
}

// ---------------------------------------------------------------------------
// Iter-0 candidates from vV: h/c + cw0.  4032 blocks.
// ---------------------------------------------------------------------------
__global__ __launch_bounds__(256) void pair_epi(
    const float* __restrict__ bcomp, const float* __restrict__ q)
{
    __shared__ float red[8];
    int pb = blockIdx.x;
    int b = pb / 63, j = pb - b * 63;
    int nl = b * NSLOT + j, nr = nl + 1, ns = b * NSLOT + 64 + j;
    int tid = threadIdx.x, lane = tid & 31, warp = tid >> 5;
    float p = 0.f;
    #pragma unroll
    for (int half = 0; half < 2; half++) {
        int hd = tid + 256 * half;
        float vg[5];
        #pragma unroll
        for (int g = 0; g < 5; g++)
            vg[g] = __ldcg(&g_V[(nl * 2 + 0) * 2560 + g * 512 + hd])
                  + __ldcg(&g_V[(nr * 2 + 1) * 2560 + g * 512 + hd])
                  + bcomp[g * 512 + hd];
        float cl = __ldcg(&g_C[nl * 512 + hd]), cr = __ldcg(&g_C[nr * 512 + hd]);
        float cn = cl * sigm(vg[1] + 1.f) + cr * sigm(vg[2] + 1.f)
                 + tanhf(vg[3]) * sigm(vg[0]);
        float hn = sigm(vg[4]) * tanhf(cn);
        g_H[ns * 512 + hd] = hn;
        g_C[ns * 512 + hd] = cn;
        p += hn * q[hd];
    }
    #pragma unroll
    for (int o = 16; o > 0; o >>= 1) p += __shfl_xor_sync(0xffffffffu, p, o);
    if (lane == 0) red[warp] = p;
    __syncthreads();
    if (tid == 0) {
        float s = 0.f;
        #pragma unroll
        for (int w = 0; w < 8; w++) s += red[w];
        g_cw0[b * 63 + j] = s;
    }
}

// ---------------------------------------------------------------------------
// Persistent loop (round-9 variant — best measured)
// ---------------------------------------------------------------------------
#define W_STRIDE 516
#define A_STRIDE 68
#define WRES_F   (40*W_STRIDE)
#define ASB_F    (64*A_STRIDE)
#define SVN_F    (64*40)
#define SMEM_BYTES ((WRES_F + 2*ASB_F + SVN_F)*4)

__global__ __launch_bounds__(TPB, 1) void tree_loop(
    const int* __restrict__ length, const float* __restrict__ q,
    const float* __restrict__ wcomp, const float* __restrict__ bcomp,
    float* __restrict__ out)
{
    extern __shared__ float smem[];
    float* Wres  = smem;
    float* Asb0  = smem + WRES_F;
    float* Asb1  = smem + WRES_F + ASB_F;
    float* sVnew = smem + WRES_F + 2*ASB_F;

    __shared__ unsigned char s_vh[BB][64];
    __shared__ unsigned char s_pk[BB][64];
    __shared__ float s_cw[BB][64];
    __shared__ int2  s_fresh[BB];
    __shared__ int   s_sel[BB];
    __shared__ int   s_nodeidx[BB];
    __shared__ int4  s_rows[128];
    __shared__ unsigned char s_rb[128], s_rln[128], s_rrn[128];
    __shared__ int   s_rcnt[BB], s_roff[BB], s_len[BB];
    __shared__ int   s_nrows, s_maxlen;

    const int tid = threadIdx.x, blk = blockIdx.x;
    const int u = tid & 3, v = tid >> 2;
    const int lane = tid & 31, warp = tid >> 5;
    const int hg = blk * 4 + u;

    for (int idx = tid; idx < 40 * 512; idx += TPB) {
        int r2 = idx >> 9, k = idx & 511;
        int side = r2 / 20, rem = r2 % 20, g = rem >> 2, hgo = rem & 3;
        Wres[r2 * W_STRIDE + k] = wcomp[(g * 512 + blk * 4 + hgo) * 1024 + side * 512 + k];
    }
    const float qv  = q[hg];
    const float bi  = bcomp[hg],        bfl = bcomp[512 + hg], bfr = bcomp[1024 + hg];
    const float bu  = bcomp[1536 + hg], bo  = bcomp[2048 + hg];

    for (int t = tid; t < BB * 64; t += TPB) {
        int b = t >> 6, j = t & 63;
        s_vh[b][j] = (unsigned char)j;
        s_pk[b][j] = (unsigned char)(64 + j);
        s_cw[b][j] = (j < 63) ? __ldcg(&g_cw0[b * 63 + j]) : -1e9f;
    }
    if (tid < BB) { s_len[tid] = length[tid]; s_fresh[tid] = make_int2(-1, -1); }
    __syncthreads();
    if (tid == 0) {
        int m = 0;
        for (int b = 0; b < BB; b++) if (s_len[b] > m) m = s_len[b];
        s_maxlen = m;
    }
    __syncthreads();
    const int maxlen = s_maxlen;

    unsigned target = 0;

    for (int i = 0; i < 63; i++) {
        if (i + 1 >= maxlen) break;
        const int n = 63 - i;

        // ---- (a) fold cw partials ----
        if (i > 0) {
            const float* cwsrc = g_cwp[i & 1];
            float4 vbuf[16];
            int    pbuf[16];
            #pragma unroll
            for (int rr = 0; rr < 16; rr++) {
                int rid = warp + 8 * rr;
                int b = rid >> 1;
                int2 fr = s_fresh[b];
                int pidx = (rid & 1) ? fr.y : fr.x;
                pbuf[rr] = pidx;
                vbuf[rr] = (pidx >= 0)
                         ? __ldcg((const float4*)&cwsrc[rid * 128 + lane * 4])
                         : make_float4(0.f, 0.f, 0.f, 0.f);
            }
            #pragma unroll
            for (int rr = 0; rr < 16; rr++) {
                if (pbuf[rr] >= 0) {
                    float4 vv = vbuf[rr];
                    float s = (vv.x + vv.y) + (vv.z + vv.w);
                    #pragma unroll
                    for (int o = 16; o > 0; o >>= 1) s += __shfl_xor_sync(0xffffffffu, s, o);
                    if (lane == 0) s_cw[(warp + 8 * rr) >> 1][pbuf[rr]] = s;
                }
            }
        }
        __syncthreads();

        // ---- (b1) select decision ----
        if (tid < BB) {
            int b = tid, len = s_len[b];
            int s;
            if (i + 1 >= len) s = -2;
            else if (n == 1) s = 0;
            else {
                float best = -2e9f; int bj = 0;
                for (int j = 0; j < n; j++) {
                    float val = (i + 1 + j < len) ? s_cw[b][j] : -1e9f;
                    if (val > best) { best = val; bj = j; }
                }
                s = bj;
            }
            s_sel[b] = s;
            int merged = -1;
            int2 fr = make_int2(-1, -1);
            if (s >= 0) {
                merged = s_pk[b][s];
                if (i < 62) {
                    if (s >= 1)     fr.x = s - 1;
                    if (s <= n - 2) fr.y = s;
                }
            }
            s_fresh[b] = fr;
            s_nodeidx[b] = (merged >= 0 && i < 62) ? (b * NSLOT + merged) : -1;
            s_rcnt[b] = (fr.x >= 0) + (fr.y >= 0);
        }
        __syncthreads();

        // ---- (b2) parallel shift: read-all, sync, write-all ----
        {
            unsigned char nvh[16], npk[16];
            float ncw[16];
            #pragma unroll
            for (int t2 = 0; t2 < 16; t2++) {
                int t = tid + 256 * t2;
                int b = t >> 6, j = t & 63;
                int s = s_sel[b];
                if (s >= 0) {
                    unsigned char vh  = s_vh[b][j];
                    unsigned char pk  = s_pk[b][j];
                    float         cw  = s_cw[b][j];
                    unsigned char vh1 = (j < 63) ? s_vh[b][j + 1] : vh;
                    unsigned char pk1 = (j < 63) ? s_pk[b][j + 1] : pk;
                    float         cw1 = (j < 63) ? s_cw[b][j + 1] : cw;
                    nvh[t2] = (j < s) ? vh : ((j == s) ? pk : vh1);
                    bool sh = (j >= s);
                    npk[t2] = sh ? pk1 : pk;
                    ncw[t2] = sh ? cw1 : cw;
                } else { nvh[t2] = 0; npk[t2] = 0; ncw[t2] = 0.f; }
            }
            __syncthreads();
            #pragma unroll
            for (int t2 = 0; t2 < 16; t2++) {
                int t = tid + 256 * t2;
                int b = t >> 6, j = t & 63;
                if (s_sel[b] >= 0) {
                    s_vh[b][j] = nvh[t2];
                    s_pk[b][j] = npk[t2];
                    s_cw[b][j] = ncw[t2];
                }
            }
        }
        __syncthreads();

        // ---- (b3) rows setup ----
        if (tid == 0) {
            int acc = 0;
            for (int b = 0; b < BB; b++) { s_roff[b] = acc; acc += s_rcnt[b]; }
            s_nrows = acc;
        }
        __syncthreads();
        if (tid < BB) {
            int b = tid; int2 fr = s_fresh[b]; int o = s_roff[b];
            if (fr.x >= 0) {
                int p = fr.x;
                s_rows[o] = make_int4(b * NSLOT + s_vh[b][p], b * NSLOT + s_vh[b][p + 1],
                                      b * NSLOT + s_pk[b][p], b * 2 + 0);
                s_rb[o] = (unsigned char)b; s_rln[o] = 0; s_rrn[o] = 1; o++;
            }
            if (fr.y >= 0) {
                int p = fr.y;
                s_rows[o] = make_int4(b * NSLOT + s_vh[b][p], b * NSLOT + s_vh[b][p + 1],
                                      b * NSLOT + s_pk[b][p], b * 2 + 1);
                s_rb[o] = (unsigned char)b; s_rln[o] = 1; s_rrn[o] = 0; o++;
            }
        }
        __syncthreads();

        const int nrows = s_nrows;

        // ---- prefetch epilogue operands ----
        float pvl[2][5], pvr[2][5], clv[2], crv[2];
        #pragma unroll
        for (int r = 0; r < 2; r++) {
            int row = v * 2 + r;
            if (row < nrows) {
                int4 ri = s_rows[row];
                clv[r] = __ldcg(&g_C[ri.x * 512 + hg]);
                crv[r] = __ldcg(&g_C[ri.y * 512 + hg]);
                if (!s_rln[row]) {
                    #pragma unroll
                    for (int g = 0; g < 5; g++)
                        pvl[r][g] = __ldcg(&g_V[(ri.x * 2 + 0) * 2560 + g * 512 + hg]);
                }
                if (!s_rrn[row]) {
                    #pragma unroll
                    for (int g = 0; g < 5; g++)
                        pvr[r][g] = __ldcg(&g_V[(ri.y * 2 + 1) * 2560 + g * 512 + hg]);
                }
            } else { clv[r] = 0.f; crv[r] = 0.f; }
        }

        // ---- (c) vV GEMM for merged nodes ----
        if (i < 62) {
            const int ni = s_nodeidx[v];
            float2 acc[10];
            #pragma unroll
            for (int a = 0; a < 10; a++) acc[a] = make_float2(0.f, 0.f);

            float4 pf[4];
            #pragma unroll
            for (int t = 0; t < 4; t++)
                pf[t] = (ni >= 0)
                      ? __ldcg((const float4*)&g_H[ni * 512 + (u + 4 * t) * 4])
                      : make_float4(0.f, 0.f, 0.f, 0.f);
            #pragma unroll
            for (int t = 0; t < 4; t++)
                ((float4*)(Asb0 + v * A_STRIDE))[u + 4 * t] = pf[t];
            __syncthreads();

            for (int c = 0; c < 8; c++) {
                if (c < 7) {
                    #pragma unroll
                    for (int t = 0; t < 4; t++)
                        pf[t] = (ni >= 0)
                              ? __ldcg((const float4*)&g_H[ni * 512 + (c + 1) * 64 + (u + 4 * t) * 4])
                              : make_float4(0.f, 0.f, 0.f, 0.f);
                }
                const float* A = (c & 1) ? Asb1 : Asb0;
                if (ni >= 0) {
                    #pragma unroll
                    for (int k4 = 0; k4 < 16; k4++) {
                        float4 av = ((const float4*)(A + v * A_STRIDE))[k4];
                        float2 alo = make_float2(av.x, av.y);
                        float2 ahi = make_float2(av.z, av.w);
                        #pragma unroll
                        for (int a = 0; a < 10; a++) {
                            int r2 = (a >= 5 ? 20 : 0) + (a % 5) * 4 + u;
                            float4 wv = ((const float4*)(Wres + r2 * W_STRIDE))[c * 16 + k4];
                            ffma2(acc[a], alo, make_float2(wv.x, wv.y));
                            ffma2(acc[a], ahi, make_float2(wv.z, wv.w));
                        }
                    }
                }
                if (c < 7) {
                    float* An = (c & 1) ? Asb0 : Asb1;
                    #pragma unroll
                    for (int t = 0; t < 4; t++)
                        ((float4*)(An + v * A_STRIDE))[u + 4 * t] = pf[t];
                }
                __syncthreads();
            }

            if (ni >= 0) {
                #pragma unroll
                for (int a = 0; a < 10; a++) {
                    int side = (a >= 5), g = a % 5;
                    float val = acc[a].x + acc[a].y;
                    sVnew[v * 40 + side * 20 + g * 4 + u] = val;
                    g_V[(ni * 2 + side) * 2560 + g * 512 + hg] = val;
                }
            }
            __syncthreads();
        }

        // ---- (d) epilogue ----
        if (nrows > 0) {
            float* cwdst = g_cwp[(i + 1) & 1];
            #pragma unroll
            for (int r = 0; r < 2; r++) {
                int row = v * 2 + r;
                float p = 0.f;
                if (row < nrows) {
                    int bb = s_rb[row];
                    float vg[5];
                    #pragma unroll
                    for (int g = 0; g < 5; g++) {
                        float L = s_rln[row] ? sVnew[bb * 40 + g * 4 + u]      : pvl[r][g];
                        float R = s_rrn[row] ? sVnew[bb * 40 + 20 + g * 4 + u] : pvr[r][g];
                        vg[g] = L + R;
                    }
                    float cn = clv[r] * sigm(vg[1] + bfl + 1.f) + crv[r] * sigm(vg[2] + bfr + 1.f)
                             + tanhf(vg[3] + bu) * sigm(vg[0] + bi);
                    float hn = sigm(vg[4] + bo) * tanhf(cn);
                    int nst = s_rows[row].z;
                    g_H[nst * 512 + hg] = hn;
                    g_C[nst * 512 + hg] = cn;
                    p = hn * qv;
                }
                p += __shfl_xor_sync(0xffffffffu, p, 1);
                p += __shfl_xor_sync(0xffffffffu, p, 2);
                if (row < nrows && u == 0) cwdst[s_rows[row].w * 128 + blk] = p;
            }
        }
        target += GRID; grid_barrier(target);
    }

    // ---- output ----
    if (blk < BB) {
        int base = (blk * NSLOT + s_vh[blk][0]) * 512;
        out[blk * 512 + tid]                  = __ldcg(&g_H[base + tid]);
        out[blk * 512 + 256 + tid]            = __ldcg(&g_H[base + 256 + tid]);
        out[BB * 512 + blk * 512 + tid]       = __ldcg(&g_C[base + tid]);
        out[BB * 512 + blk * 512 + 256 + tid] = __ldcg(&g_C[base + 256 + tid]);
    }
}

// ---------------------------------------------------------------------------
extern "C" void kernel_launch(void* const* d_in, const int* in_sizes, int n_in,
                              void* d_out, int out_size)
{
    const float* x      = (const float*)d_in[0];
    const int*   length = (const int*)  d_in[1];
    const float* w_word = (const float*)d_in[2];
    const float* b_word = (const float*)d_in[3];
    const float* w_comp = (const float*)d_in[4];
    const float* b_comp = (const float*)d_in[5];
    const float* q      = (const float*)d_in[6];
    float* out = (float*)d_out;

    static int smem_set = 0;
    if (!smem_set) {
        cudaFuncSetAttribute(tree_loop, cudaFuncAttributeMaxDynamicSharedMemorySize,
                             SMEM_BYTES);
        smem_set = 1;
    }

    word_gemm<<<dim3(16, 64), 256>>>(x, w_word, b_word);
    vv_full<<<dim3(128, 32), 256>>>(w_comp);
    pair_epi<<<4032, 256>>>(b_comp, q);
    tree_loop<<<GRID, TPB, SMEM_BYTES>>>(length, q, w_comp, b_comp, out);
}

// round 14
// speedup vs baseline: 1.0681x; 1.0077x over previous
#include <cuda_runtime.h>
#include <cstdint>
#include <math.h>

#define BB 64
#define GRID 128
#define TPB 256
#define NSLOT 128
#define NST (BB*NSLOT*512)

__device__ float g_H[NST];
__device__ float g_C[NST];
// vV cache: [b][slot][side][2560] ; side0 = W_l@h, side1 = W_r@h
__device__ float g_V[BB*NSLOT*2*2560];
__device__ float g_cwp[2][128*128];   // cw partials, parity double-buffered
__device__ float g_cw0[BB*63];
__device__ unsigned g_cnt;
__device__ unsigned g_gen;

__device__ __forceinline__ float sigm(float x){ return 1.0f/(1.0f+expf(-x)); }

__device__ __forceinline__ void ffma2(float2 &acc, float2 a, float2 b){
    asm("fma.rn.f32x2 %0, %1, %2, %0;"
        : "+l"(reinterpret_cast<unsigned long long&>(acc))
        : "l"(reinterpret_cast<unsigned long long&>(a)),
          "l"(reinterpret_cast<unsigned long long&>(b)));
}

__device__ __forceinline__ void cp16(unsigned s, const void* g){
    asm volatile("cp.async.ca.shared.global [%0], [%1], 16;\n" :: "r"(s), "l"(g));
}

// single-counter release/acquire barrier; last arriver publishes generation
__device__ __forceinline__ void grid_barrier(unsigned target){
    __syncthreads();
    if (threadIdx.x == 0){
        unsigned old;
        asm volatile("atom.release.gpu.global.add.u32 %0, [%1], 1;"
                     : "=r"(old) : "l"(&g_cnt) : "memory");
        if (old == target - 1u) {
            asm volatile("st.release.gpu.global.u32 [%0], %1;"
                         :: "l"(&g_gen), "r"(target) : "memory");
        } else {
            unsigned g;
            do {
                asm volatile("ld.acquire.gpu.global.u32 %0, [%1];"
                             : "=r"(g) : "l"(&g_gen) : "memory");
            } while (g < target);
        }
    }
    __syncthreads();
}

// ---------------------------------------------------------------------------
// Word GEMM (f32x2, transposed W tile); also zeroes barrier state
// ---------------------------------------------------------------------------
__global__ __launch_bounds__(256) void word_gemm(
    const float* __restrict__ x, const float* __restrict__ w,
    const float* __restrict__ bias)
{
    if (blockIdx.x == 0 && blockIdx.y == 0 && threadIdx.x == 0) {
        g_cnt = 0u; g_gen = 0u;
    }

    __shared__ float As[64][33];
    __shared__ float Wt[32][68];
    int tid = threadIdx.x;
    int tx = tid & 15, ty = tid >> 4;
    int m0 = blockIdx.y * 64;
    int c0 = blockIdx.x * 64;
    const int lr = tid >> 5, kkld = tid & 31;

    float2 acc[4][2];
    #pragma unroll
    for (int r = 0; r < 4; r++){ acc[r][0] = make_float2(0.f,0.f); acc[r][1] = make_float2(0.f,0.f); }

    for (int k0 = 0; k0 < 512; k0 += 32) {
        #pragma unroll
        for (int t = 0; t < 8; t++) {
            int r = lr + 8 * t;
            As[r][kkld] = x[(m0 + r) * 512 + k0 + kkld];
            Wt[kkld][r] = w[(c0 + r) * 512 + k0 + kkld];
        }
        __syncthreads();
        #pragma unroll
        for (int kk = 0; kk < 32; kk++) {
            float4 wv = *(const float4*)&Wt[kk][tx * 4];
            #pragma unroll
            for (int r = 0; r < 4; r++) {
                float a = As[ty * 4 + r][kk];
                ffma2(acc[r][0], make_float2(a, a), make_float2(wv.x, wv.y));
                ffma2(acc[r][1], make_float2(a, a), make_float2(wv.z, wv.w));
            }
        }
        __syncthreads();
    }
    #pragma unroll
    for (int r = 0; r < 4; r++) {
        int m = m0 + ty * 4 + r;
        int b = m >> 6, leaf = m & 63;
        int base = (b * NSLOT + leaf) * 512;
        #pragma unroll
        for (int c2 = 0; c2 < 2; c2++) {
            #pragma unroll
            for (int e = 0; e < 2; e++) {
                int col = c0 + tx * 4 + c2 * 2 + e;
                float v = (e ? acc[r][c2].y : acc[r][c2].x) + bias[col];
                if (col < 512) g_H[base + col] = v;
                else           g_C[base + col - 512] = v;
            }
        }
    }
}

// ---------------------------------------------------------------------------
// vV for all 4096 leaf nodes: cp.async double-buffered, 2 blocks/SM
// ---------------------------------------------------------------------------
__global__ __launch_bounds__(256) void vv_full(const float* __restrict__ wcomp)
{
    __shared__ float As[2][128*36];
    __shared__ float Ws[2][40*36];
    const int tid = threadIdx.x;
    const int tx = tid & 7, ty = tid >> 3;
    const int side = blockIdx.x & 1;
    const int h0 = (blockIdx.x >> 1) * 8;
    const int m0 = blockIdx.y * 128;

    int arow[4], aq[4];
    const float* asrc[4];
    #pragma unroll
    for (int ii = 0; ii < 4; ii++) {
        int f = tid + 256 * ii; int row = f >> 3; int qd = f & 7;
        arow[ii] = row; aq[ii] = qd;
        int rg = m0 + row; int b = rg >> 6, leaf = rg & 63;
        asrc[ii] = &g_H[(b * NSLOT + leaf) * 512 + qd * 4];
    }
    int wrow[2], wq[2]; bool wok[2];
    const float* wsrc[2];
    #pragma unroll
    for (int tt = 0; tt < 2; tt++) {
        int f = tid + 256 * tt; wok[tt] = (f < 320);
        int r2 = f >> 3, qd = f & 7;
        wrow[tt] = r2; wq[tt] = qd;
        int g = r2 >> 3, hh = r2 & 7;
        wsrc[tt] = wok[tt]
                 ? &wcomp[(g * 512 + h0 + hh) * 1024 + side * 512 + qd * 4]
                 : wcomp;
    }

    float2 acc[4][5];
    #pragma unroll
    for (int r = 0; r < 4; r++)
        #pragma unroll
        for (int g = 0; g < 5; g++) acc[r][g] = make_float2(0.f, 0.f);

    {
        #pragma unroll
        for (int ii = 0; ii < 4; ii++)
            cp16((unsigned)__cvta_generic_to_shared(&As[0][arow[ii]*36 + aq[ii]*4]), asrc[ii]);
        #pragma unroll
        for (int tt = 0; tt < 2; tt++)
            if (wok[tt])
                cp16((unsigned)__cvta_generic_to_shared(&Ws[0][wrow[tt]*36 + wq[tt]*4]), wsrc[tt]);
        asm volatile("cp.async.commit_group;\n");
    }

    for (int c = 0; c < 16; c++) {
        if (c < 15) {
            int koff = (c + 1) * 32;
            int buf = (c + 1) & 1;
            #pragma unroll
            for (int ii = 0; ii < 4; ii++)
                cp16((unsigned)__cvta_generic_to_shared(&As[buf][arow[ii]*36 + aq[ii]*4]), asrc[ii] + koff);
            #pragma unroll
            for (int tt = 0; tt < 2; tt++)
                if (wok[tt])
                    cp16((unsigned)__cvta_generic_to_shared(&Ws[buf][wrow[tt]*36 + wq[tt]*4]), wsrc[tt] + koff);
            asm volatile("cp.async.commit_group;\n");
            asm volatile("cp.async.wait_group 1;\n");
        } else {
            asm volatile("cp.async.wait_group 0;\n");
        }
        __syncthreads();
        const float* A = As[c & 1];
        const float* W = Ws[c & 1];
        #pragma unroll
        for (int k4 = 0; k4 < 8; k4++) {
            float4 wv[5];
            #pragma unroll
            for (int g = 0; g < 5; g++)
                wv[g] = ((const float4*)(W + (g * 8 + tx) * 36))[k4];
            #pragma unroll
            for (int r = 0; r < 4; r++) {
                float4 av = ((const float4*)(A + (ty * 4 + r) * 36))[k4];
                #pragma unroll
                for (int g = 0; g < 5; g++) {
                    ffma2(acc[r][g], make_float2(av.x, av.y), make_float2(wv[g].x, wv[g].y));
                    ffma2(acc[r][g], make_float2(av.z, av.w), make_float2(wv[g].z, wv[g].w));
                }
            }
        }
        __syncthreads();
    }

    #pragma unroll
    for (int r = 0; r < 4; r++) {
        int row = m0 + ty * 4 + r;
        int b = row >> 6, leaf = row & 63;
        int vbase = ((b * NSLOT + leaf) * 2 + side) * 2560;
        #pragma unroll
        for (int g = 0; g < 5; g++)
            g_V[vbase + g * 512 + h0 + tx] = acc[r][g].x + acc[r][g].y;
    }
}

// ---------------------------------------------------------------------------
// Iter-0 candidates from vV: h/c + cw0.  4032 blocks.
// ---------------------------------------------------------------------------
__global__ __launch_bounds__(256) void pair_epi(
    const float* __restrict__ bcomp, const float* __restrict__ q)
{
    __shared__ float red[8];
    int pb = blockIdx.x;
    int b = pb / 63, j = pb - b * 63;
    int nl = b * NSLOT + j, nr = nl + 1, ns = b * NSLOT + 64 + j;
    int tid = threadIdx.x, lane = tid & 31, warp = tid >> 5;
    float p = 0.f;
    #pragma unroll
    for (int half = 0; half < 2; half++) {
        int hd = tid + 256 * half;
        float vg[5];
        #pragma unroll
        for (int g = 0; g < 5; g++)
            vg[g] = __ldcg(&g_V[(nl * 2 + 0) * 2560 + g * 512 + hd])
                  + __ldcg(&g_V[(nr * 2 + 1) * 2560 + g * 512 + hd])
                  + bcomp[g * 512 + hd];
        float cl = __ldcg(&g_C[nl * 512 + hd]), cr = __ldcg(&g_C[nr * 512 + hd]);
        float cn = cl * sigm(vg[1] + 1.f) + cr * sigm(vg[2] + 1.f)
                 + tanhf(vg[3]) * sigm(vg[0]);
        float hn = sigm(vg[4]) * tanhf(cn);
        g_H[ns * 512 + hd] = hn;
        g_C[ns * 512 + hd] = cn;
        p += hn * q[hd];
    }
    #pragma unroll
    for (int o = 16; o > 0; o >>= 1) p += __shfl_xor_sync(0xffffffffu, p, o);
    if (lane == 0) red[warp] = p;
    __syncthreads();
    if (tid == 0) {
        float s = 0.f;
        #pragma unroll
        for (int w = 0; w < 8; w++) s += red[w];
        g_cw0[b * 63 + j] = s;
    }
}

// ---------------------------------------------------------------------------
// Persistent loop: parallel select, warp-scan offsets, 1-counter barrier
// ---------------------------------------------------------------------------
#define W_STRIDE 516
#define A_STRIDE 68
#define WRES_F   (40*W_STRIDE)
#define ASB_F    (64*A_STRIDE)
#define SVN_F    (64*40)
#define SMEM_BYTES ((WRES_F + 2*ASB_F + SVN_F)*4)

__global__ __launch_bounds__(TPB, 1) void tree_loop(
    const int* __restrict__ length, const float* __restrict__ q,
    const float* __restrict__ wcomp, const float* __restrict__ bcomp,
    float* __restrict__ out)
{
    extern __shared__ float smem[];
    float* Wres  = smem;
    float* Asb0  = smem + WRES_F;
    float* Asb1  = smem + WRES_F + ASB_F;
    float* sVnew = smem + WRES_F + 2*ASB_F;

    __shared__ unsigned char s_vh[BB][64];
    __shared__ unsigned char s_pk[BB][64];
    __shared__ float s_cw[BB][64];
    __shared__ int2  s_fresh[BB];
    __shared__ int   s_sel[BB];
    __shared__ int   s_nodeidx[BB];
    __shared__ int4  s_rows[128];
    __shared__ unsigned char s_rb[128], s_rln[128], s_rrn[128];
    __shared__ int   s_rcnt[BB], s_roff[BB], s_len[BB];
    __shared__ int   s_wtot[2];
    __shared__ int   s_nrows, s_maxlen;

    const int tid = threadIdx.x, blk = blockIdx.x;
    const int u = tid & 3, v = tid >> 2;
    const int lane = tid & 31, warp = tid >> 5;
    const int hg = blk * 4 + u;

    for (int idx = tid; idx < 40 * 512; idx += TPB) {
        int r2 = idx >> 9, k = idx & 511;
        int side = r2 / 20, rem = r2 % 20, g = rem >> 2, hgo = rem & 3;
        Wres[r2 * W_STRIDE + k] = wcomp[(g * 512 + blk * 4 + hgo) * 1024 + side * 512 + k];
    }
    const float qv  = q[hg];
    const float bi  = bcomp[hg],        bfl = bcomp[512 + hg], bfr = bcomp[1024 + hg];
    const float bu  = bcomp[1536 + hg], bo  = bcomp[2048 + hg];

    for (int t = tid; t < BB * 64; t += TPB) {
        int b = t >> 6, j = t & 63;
        s_vh[b][j] = (unsigned char)j;
        s_pk[b][j] = (unsigned char)(64 + j);
        s_cw[b][j] = (j < 63) ? __ldcg(&g_cw0[b * 63 + j]) : -1e9f;
    }
    if (tid < BB) { s_len[tid] = length[tid]; s_fresh[tid] = make_int2(-1, -1); }
    __syncthreads();
    if (tid == 0) {
        int m = 0;
        for (int b = 0; b < BB; b++) if (s_len[b] > m) m = s_len[b];
        s_maxlen = m;
    }
    __syncthreads();
    const int maxlen = s_maxlen;

    unsigned target = 0;

    for (int i = 0; i < 63; i++) {
        if (i + 1 >= maxlen) break;
        const int n = 63 - i;

        // ---- (a) fold cw partials ----
        if (i > 0) {
            const float* cwsrc = g_cwp[i & 1];
            float4 vbuf[16];
            int    pbuf[16];
            #pragma unroll
            for (int rr = 0; rr < 16; rr++) {
                int rid = warp + 8 * rr;
                int b = rid >> 1;
                int2 fr = s_fresh[b];
                int pidx = (rid & 1) ? fr.y : fr.x;
                pbuf[rr] = pidx;
                vbuf[rr] = (pidx >= 0)
                         ? __ldcg((const float4*)&cwsrc[rid * 128 + lane * 4])
                         : make_float4(0.f, 0.f, 0.f, 0.f);
            }
            #pragma unroll
            for (int rr = 0; rr < 16; rr++) {
                if (pbuf[rr] >= 0) {
                    float4 vv = vbuf[rr];
                    float s = (vv.x + vv.y) + (vv.z + vv.w);
                    #pragma unroll
                    for (int o = 16; o > 0; o >>= 1) s += __shfl_xor_sync(0xffffffffu, s, o);
                    if (lane == 0) s_cw[(warp + 8 * rr) >> 1][pbuf[rr]] = s;
                }
            }
        }
        __syncthreads();

        // ---- (b1) parallel select: 4 threads/batch, first-max semantics ----
        {
            int b = tid >> 2, p = tid & 3;
            int len = s_len[b];
            float bv = -2e9f; int bj = 0;
            int j0 = p * 16;
            int j1 = j0 + 16; if (j1 > n) j1 = n;
            for (int j = j0; j < j1; j++) {
                float val = (i + 1 + j < len) ? s_cw[b][j] : -1e9f;
                if (val > bv) { bv = val; bj = j; }
            }
            #pragma unroll
            for (int o = 1; o <= 2; o <<= 1) {
                float ov = __shfl_xor_sync(0xffffffffu, bv, o);
                int   oj = __shfl_xor_sync(0xffffffffu, bj, o);
                if (ov > bv || (ov == bv && oj < bj)) { bv = ov; bj = oj; }
            }
            if (p == 0) {
                int s;
                if (i + 1 >= len) s = -2;
                else if (n == 1) s = 0;
                else s = bj;
                s_sel[b] = s;
                int merged = -1;
                int2 fr = make_int2(-1, -1);
                if (s >= 0) {
                    merged = s_pk[b][s];
                    if (i < 62) {
                        if (s >= 1)     fr.x = s - 1;
                        if (s <= n - 2) fr.y = s;
                    }
                }
                s_fresh[b] = fr;
                s_nodeidx[b] = (merged >= 0 && i < 62) ? (b * NSLOT + merged) : -1;
                s_rcnt[b] = (fr.x >= 0) + (fr.y >= 0);
            }
        }
        __syncthreads();

        // ---- (b2) parallel shift: read-all, sync, write-all ----
        {
            unsigned char nvh[16], npk[16];
            float ncw[16];
            #pragma unroll
            for (int t2 = 0; t2 < 16; t2++) {
                int t = tid + 256 * t2;
                int b = t >> 6, j = t & 63;
                int s = s_sel[b];
                if (s >= 0) {
                    unsigned char vh  = s_vh[b][j];
                    unsigned char pk  = s_pk[b][j];
                    float         cw  = s_cw[b][j];
                    unsigned char vh1 = (j < 63) ? s_vh[b][j + 1] : vh;
                    unsigned char pk1 = (j < 63) ? s_pk[b][j + 1] : pk;
                    float         cw1 = (j < 63) ? s_cw[b][j + 1] : cw;
                    nvh[t2] = (j < s) ? vh : ((j == s) ? pk : vh1);
                    bool sh = (j >= s);
                    npk[t2] = sh ? pk1 : pk;
                    ncw[t2] = sh ? cw1 : cw;
                } else { nvh[t2] = 0; npk[t2] = 0; ncw[t2] = 0.f; }
            }
            __syncthreads();
            #pragma unroll
            for (int t2 = 0; t2 < 16; t2++) {
                int t = tid + 256 * t2;
                int b = t >> 6, j = t & 63;
                if (s_sel[b] >= 0) {
                    s_vh[b][j] = nvh[t2];
                    s_pk[b][j] = npk[t2];
                    s_cw[b][j] = ncw[t2];
                }
            }
        }
        __syncthreads();

        // ---- (b3) rows offsets via warp scan (warp0: b<32, warp1: b>=32) ----
        if (tid < 64) {
            int cnt = s_rcnt[tid];
            int sc = cnt;
            #pragma unroll
            for (int o = 1; o < 32; o <<= 1) {
                int t = __shfl_up_sync(0xffffffffu, sc, o);
                if (lane >= o) sc += t;
            }
            s_roff[tid] = sc - cnt;
            if (lane == 31) s_wtot[tid >> 5] = sc;
        }
        __syncthreads();
        if (tid >= 32 && tid < 64) s_roff[tid] += s_wtot[0];
        if (tid == 0) s_nrows = s_wtot[0] + s_wtot[1];
        __syncthreads();
        if (tid < BB) {
            int b = tid; int2 fr = s_fresh[b]; int o = s_roff[b];
            if (fr.x >= 0) {
                int p = fr.x;
                s_rows[o] = make_int4(b * NSLOT + s_vh[b][p], b * NSLOT + s_vh[b][p + 1],
                                      b * NSLOT + s_pk[b][p], b * 2 + 0);
                s_rb[o] = (unsigned char)b; s_rln[o] = 0; s_rrn[o] = 1; o++;
            }
            if (fr.y >= 0) {
                int p = fr.y;
                s_rows[o] = make_int4(b * NSLOT + s_vh[b][p], b * NSLOT + s_vh[b][p + 1],
                                      b * NSLOT + s_pk[b][p], b * 2 + 1);
                s_rb[o] = (unsigned char)b; s_rln[o] = 1; s_rrn[o] = 0; o++;
            }
        }
        __syncthreads();

        const int nrows = s_nrows;

        // ---- prefetch epilogue operands (hidden under GEMM) ----
        float pvl[2][5], pvr[2][5], clv[2], crv[2];
        #pragma unroll
        for (int r = 0; r < 2; r++) {
            int row = v * 2 + r;
            if (row < nrows) {
                int4 ri = s_rows[row];
                clv[r] = __ldcg(&g_C[ri.x * 512 + hg]);
                crv[r] = __ldcg(&g_C[ri.y * 512 + hg]);
                if (!s_rln[row]) {
                    #pragma unroll
                    for (int g = 0; g < 5; g++)
                        pvl[r][g] = __ldcg(&g_V[(ri.x * 2 + 0) * 2560 + g * 512 + hg]);
                }
                if (!s_rrn[row]) {
                    #pragma unroll
                    for (int g = 0; g < 5; g++)
                        pvr[r][g] = __ldcg(&g_V[(ri.y * 2 + 1) * 2560 + g * 512 + hg]);
                }
            } else { clv[r] = 0.f; crv[r] = 0.f; }
        }

        // ---- (c) vV GEMM for merged nodes ----
        if (i < 62) {
            const int ni = s_nodeidx[v];
            float2 acc[10];
            #pragma unroll
            for (int a = 0; a < 10; a++) acc[a] = make_float2(0.f, 0.f);

            float4 pf[4];
            #pragma unroll
            for (int t = 0; t < 4; t++)
                pf[t] = (ni >= 0)
                      ? __ldcg((const float4*)&g_H[ni * 512 + (u + 4 * t) * 4])
                      : make_float4(0.f, 0.f, 0.f, 0.f);
            #pragma unroll
            for (int t = 0; t < 4; t++)
                ((float4*)(Asb0 + v * A_STRIDE))[u + 4 * t] = pf[t];
            __syncthreads();

            for (int c = 0; c < 8; c++) {
                if (c < 7) {
                    #pragma unroll
                    for (int t = 0; t < 4; t++)
                        pf[t] = (ni >= 0)
                              ? __ldcg((const float4*)&g_H[ni * 512 + (c + 1) * 64 + (u + 4 * t) * 4])
                              : make_float4(0.f, 0.f, 0.f, 0.f);
                }
                const float* A = (c & 1) ? Asb1 : Asb0;
                if (ni >= 0) {
                    #pragma unroll
                    for (int k4 = 0; k4 < 16; k4++) {
                        float4 av = ((const float4*)(A + v * A_STRIDE))[k4];
                        float2 alo = make_float2(av.x, av.y);
                        float2 ahi = make_float2(av.z, av.w);
                        #pragma unroll
                        for (int a = 0; a < 10; a++) {
                            int r2 = (a >= 5 ? 20 : 0) + (a % 5) * 4 + u;
                            float4 wv = ((const float4*)(Wres + r2 * W_STRIDE))[c * 16 + k4];
                            ffma2(acc[a], alo, make_float2(wv.x, wv.y));
                            ffma2(acc[a], ahi, make_float2(wv.z, wv.w));
                        }
                    }
                }
                if (c < 7) {
                    float* An = (c & 1) ? Asb0 : Asb1;
                    #pragma unroll
                    for (int t = 0; t < 4; t++)
                        ((float4*)(An + v * A_STRIDE))[u + 4 * t] = pf[t];
                }
                __syncthreads();
            }

            if (ni >= 0) {
                #pragma unroll
                for (int a = 0; a < 10; a++) {
                    int side = (a >= 5), g = a % 5;
                    float val = acc[a].x + acc[a].y;
                    sVnew[v * 40 + side * 20 + g * 4 + u] = val;
                    g_V[(ni * 2 + side) * 2560 + g * 512 + hg] = val;
                }
            }
            __syncthreads();
        }

        // ---- (d) epilogue ----
        if (nrows > 0) {
            float* cwdst = g_cwp[(i + 1) & 1];
            #pragma unroll
            for (int r = 0; r < 2; r++) {
                int row = v * 2 + r;
                float p = 0.f;
                if (row < nrows) {
                    int bb = s_rb[row];
                    float vg[5];
                    #pragma unroll
                    for (int g = 0; g < 5; g++) {
                        float L = s_rln[row] ? sVnew[bb * 40 + g * 4 + u]      : pvl[r][g];
                        float R = s_rrn[row] ? sVnew[bb * 40 + 20 + g * 4 + u] : pvr[r][g];
                        vg[g] = L + R;
                    }
                    float cn = clv[r] * sigm(vg[1] + bfl + 1.f) + crv[r] * sigm(vg[2] + bfr + 1.f)
                             + tanhf(vg[3] + bu) * sigm(vg[0] + bi);
                    float hn = sigm(vg[4] + bo) * tanhf(cn);
                    int nst = s_rows[row].z;
                    g_H[nst * 512 + hg] = hn;
                    g_C[nst * 512 + hg] = cn;
                    p = hn * qv;
                }
                p += __shfl_xor_sync(0xffffffffu, p, 1);
                p += __shfl_xor_sync(0xffffffffu, p, 2);
                if (row < nrows && u == 0) cwdst[s_rows[row].w * 128 + blk] = p;
            }
        }
        target += GRID; grid_barrier(target);
    }

    // ---- output ----
    if (blk < BB) {
        int base = (blk * NSLOT + s_vh[blk][0]) * 512;
        out[blk * 512 + tid]                  = __ldcg(&g_H[base + tid]);
        out[blk * 512 + 256 + tid]            = __ldcg(&g_H[base + 256 + tid]);
        out[BB * 512 + blk * 512 + tid]       = __ldcg(&g_C[base + tid]);
        out[BB * 512 + blk * 512 + 256 + tid] = __ldcg(&g_C[base + 256 + tid]);
    }
}

// ---------------------------------------------------------------------------
extern "C" void kernel_launch(void* const* d_in, const int* in_sizes, int n_in,
                              void* d_out, int out_size)
{
    const float* x      = (const float*)d_in[0];
    const int*   length = (const int*)  d_in[1];
    const float* w_word = (const float*)d_in[2];
    const float* b_word = (const float*)d_in[3];
    const float* w_comp = (const float*)d_in[4];
    const float* b_comp = (const float*)d_in[5];
    const float* q      = (const float*)d_in[6];
    float* out = (float*)d_out;

    static int smem_set = 0;
    if (!smem_set) {
        cudaFuncSetAttribute(tree_loop, cudaFuncAttributeMaxDynamicSharedMemorySize,
                             SMEM_BYTES);
        smem_set = 1;
    }

    word_gemm<<<dim3(16, 64), 256>>>(x, w_word, b_word);
    vv_full<<<dim3(128, 32), 256>>>(w_comp);
    pair_epi<<<4032, 256>>>(b_comp, q);
    tree_loop<<<GRID, TPB, SMEM_BYTES>>>(length, q, w_comp, b_comp, out);
}